// round 16
// baseline (speedup 1.0000x reference)
#include <cuda_runtime.h>
#include <math.h>

// WaterNetModel: chunk-parallel scan, fused persistent kernel.
// Round 16: R15 base + (1) D-accumulator rescale (E'=fma(c1,E,t1), D=cg*E at
// end: -1 FMUL/bucket/step in C), (2) two independent barriers with
// arrive-only fast path for chunk-0 blocks (they depend on nothing; their
// stores fill DRAM during others' waits; no polling traffic), (3) chunk-15
// A-summaries skipped (never read).
// Snow: s' = max(s + a, b) (max-plus); A = Psum - melt*Tsum.
// Bucket: h' = c1*(h + xin), constant c1 (affine).
// Outputs: Q [NT,NS] | H [NT,NS,NH] | S [NT,NS,NH].

#define NT 1096
#define NS 2048
#define NH 16
#define C16 16
#define CA 32
#define LANES (NS * NH)        // 32768
#define L4    (LANES / 4)      // 8192
#define NTHREADS (C16 * L4)    // 131072
#define BLK 128
#define NBLOCKS (NTHREADS / BLK)  // 1024 (<= 8*148 = 1184 resident slots)

// scratch
__device__ float g_Ps[CA * NS];          // per-A-chunk sum of pneg
__device__ float g_Ts[CA * NS];          // per-A-chunk sum of tpos
__device__ float g_B[CA * LANES];        // snow compose floor
__device__ float g_sstart[C16 * LANES];  // C-chunk start snow state (self-RW)
__device__ float g_D[C16 * LANES];       // bucket chunk offsets

// two independent gen-counter barriers (monotonic gens -> replay-safe)
__device__ unsigned g_bar1 = 0, g_gen1 = 0;
__device__ unsigned g_bar2 = 0, g_gen2 = 0;

__device__ __forceinline__ void barrier_sync(unsigned* bar, unsigned* gen,
                                             bool wait_release)
{
    __syncthreads();
    if (threadIdx.x == 0) {
        __threadfence();
        unsigned g0 = *(volatile unsigned*)gen;
        unsigned arr = atomicAdd(bar, 1u);
        if (arr == (unsigned)gridDim.x - 1u) {
            *bar = 0;
            __threadfence();
            *(volatile unsigned*)gen = g0 + 1u;
        } else if (wait_release) {
            while (*(volatile unsigned*)gen == g0) { __nanosleep(32); }
        }
        __threadfence();
    }
    __syncthreads();
}

// C-chunk geometry: chunks 0..13 len 68, chunks 14..15 len 72
__device__ __forceinline__ int c_t0(int c)  { return (c < 14) ? 68 * c : 952 + 72 * (c - 14); }
__device__ __forceinline__ int c_len(int c) { return (c < 14) ? 68 : 72; }

__global__ __launch_bounds__(BLK, 8)
void waternet_fused(const float* __restrict__ P, const float* __restrict__ T,
                    const float* __restrict__ w_i, const float* __restrict__ w_o,
                    const float* __restrict__ w_l, const float* __restrict__ w_s,
                    float* __restrict__ Q, float* __restrict__ H,
                    float* __restrict__ S)
{
    // time-packed slab: sm[t4][site] = float4 of 4 consecutive timesteps
    __shared__ float4 smP4[18 * 32];   // 9 KB
    __shared__ float4 smT4[18 * 32];   // 9 KB

    const int tid = threadIdx.x;
    const int g   = blockIdx.x * BLK + tid;   // [0, NTHREADS)

    const int lane4 = g & (L4 - 1);
    const int chunk = g >> 13;
    const int site  = lane4 >> 2;
    const int bg    = tid & 3;
    const int b0    = bg * 4;
    const int sl    = tid >> 2;                // local site [0,32)

    const int t0  = c_t0(chunk);
    const int len = c_len(chunk);
    const int nG  = len >> 2;                  // 17 or 18 groups of 4

    // =============== Stage slab (once; reused by A, C, E) ================
    {
        const int s0 = ((blockIdx.x * BLK) & (L4 - 1)) >> 2;
        const int nE = nG * 32;
        for (int e = tid; e < nE; e += BLK) {
            const int t4 = e >> 5, j = e & 31;
            const float* Pg = P + (t0 + 4 * t4) * NS + s0 + j;
            const float* Tg = T + (t0 + 4 * t4) * NS + s0 + j;
            float4 p, t;
            p.x = __ldg(Pg);          t.x = __ldg(Tg);
            p.y = __ldg(Pg + NS);     t.y = __ldg(Tg + NS);
            p.z = __ldg(Pg + 2 * NS); t.z = __ldg(Tg + 2 * NS);
            p.w = __ldg(Pg + 3 * NS); t.w = __ldg(Tg + 3 * NS);
            smP4[t4 * 32 + j] = p;
            smT4[t4 * 32 + j] = t;
        }
    }

    float melt[4];
    #pragma unroll
    for (int j = 0; j < 4; j++) melt[j] = expf(w_s[b0 + j]) + 1.0f;

    __syncthreads();

    // =============== Phase A: own chunk's two half-summaries =============
    // chunk 15's summaries are never folded by anyone -> skip
    if (chunk != C16 - 1) {
        #pragma unroll
        for (int hlf = 0; hlf < 2; hlf++) {
            const int t40 = hlf ? 9 : 0;       // halves [0,36) and [36,len)
            const int t41 = hlf ? nG : 9;
            float B[4] = {-INFINITY, -INFINITY, -INFINITY, -INFINITY};
            float Ps = 0.0f, Ts = 0.0f;
            for (int t4 = t40; t4 < t41; t4++) {
                const float4 P4 = smP4[t4 * 32 + sl];
                const float4 T4 = smT4[t4 * 32 + sl];
                const float* Pv = &P4.x;
                const float* Tv = &T4.x;
                #pragma unroll
                for (int u = 0; u < 4; u++) {
                    const float tpos = fmaxf(Tv[u], 0.0f);
                    const float pneg = (Tv[u] < 0.0f) ? Pv[u] : 0.0f;
                    Ps += pneg;
                    Ts += tpos;
                    #pragma unroll
                    for (int j = 0; j < 4; j++) {
                        const float a = fmaf(tpos, -melt[j], pneg);
                        B[j] = fmaxf(B[j] + a, pneg);
                    }
                }
            }
            const int ca = 2 * chunk + hlf;
            ((float4*)g_B)[ca * L4 + lane4] = make_float4(B[0], B[1], B[2], B[3]);
            if (bg == 0) {
                g_Ps[ca * NS + site] = Ps;
                g_Ts[ca * NS + site] = Ts;
            }
        }
    }
    // barrier 1: everyone arrives; chunk 0 doesn't wait (folds nothing)
    barrier_sync(&g_bar1, &g_gen1, chunk != 0);

    // =============== Phase C: fold s_start, replay snow, write S =========
    {
        float c1[4], cg[4];
        #pragma unroll
        for (int j = 0; j < 4; j++) {
            const float gi = 1.0f / (1.0f + expf(-w_i[b0 + j]));
            c1[j] = 1.0f - 1.0f / (1.0f + expf(-w_l[b0 + j]));
            cg[j] = c1[j] * gi;
        }

        // distributed s_start fold over preceding A-chunks
        float s[4] = {0, 0, 0, 0};
        {
            const int nca = chunk * 2;
            #pragma unroll 2
            for (int ca = 0; ca < nca; ca++) {
                const float Ps = g_Ps[ca * NS + site];
                const float Ts = g_Ts[ca * NS + site];
                const float4 B = ((const float4*)g_B)[ca * L4 + lane4];
                s[0] = fmaxf(s[0] + fmaf(-melt[0], Ts, Ps), B.x);
                s[1] = fmaxf(s[1] + fmaf(-melt[1], Ts, Ps), B.y);
                s[2] = fmaxf(s[2] + fmaf(-melt[2], Ts, Ps), B.z);
                s[3] = fmaxf(s[3] + fmaf(-melt[3], Ts, Ps), B.w);
            }
        }
        ((float4*)g_sstart)[chunk * L4 + lane4] = make_float4(s[0], s[1], s[2], s[3]);

        // rescaled bucket accumulator: E' = fma(c1, E, t1); D = cg*E at end
        float E[4] = {0, 0, 0, 0};
        float4* S4 = (float4*)S + (size_t)t0 * L4 + lane4;

        #pragma unroll 2
        for (int t4 = 0; t4 < nG; t4++) {
            const float4 P4 = smP4[t4 * 32 + sl];
            const float4 T4 = smT4[t4 * 32 + sl];
            const float* Pv = &P4.x;
            const float* Tv = &T4.x;
            #pragma unroll
            for (int u = 0; u < 4; u++) {
                const int k = t4 * 4 + u;
                const float tpos = fmaxf(Tv[u], 0.0f);
                const float pneg = (Tv[u] < 0.0f) ? Pv[u] : 0.0f;
                const float ppos = (Tv[u] > 0.0f) ? Pv[u] : 0.0f;
                float sn[4];
                #pragma unroll
                for (int j = 0; j < 4; j++) {
                    const float sm = tpos * melt[j];
                    const float m  = fminf(sm, s[j]);
                    sn[j] = (s[j] - m) + pneg;
                    E[j] = fmaf(c1[j], E[j], ppos + m);
                    s[j] = sn[j];
                }
                __stcs(&S4[(size_t)k * L4], make_float4(sn[0], sn[1], sn[2], sn[3]));
            }
        }
        ((float4*)g_D)[chunk * L4 + lane4] =
            make_float4(cg[0] * E[0], cg[1] * E[1], cg[2] * E[2], cg[3] * E[3]);
    }
    // barrier 2: everyone arrives; chunk 0 doesn't wait (reads no g_D)
    barrier_sync(&g_bar2, &g_gen2, chunk != 0);

    // =============== Phase E: h_start fold, replay, write H and Q ========
    {
        float gi[4], c1[4], glaw[4];
        {
            float mx = w_o[0];
            #pragma unroll
            for (int j = 1; j < NH; j++) mx = fmaxf(mx, w_o[j]);
            float ssum = 0.0f;
            #pragma unroll
            for (int j = 0; j < NH; j++) ssum += expf(w_o[j] - mx);
            #pragma unroll
            for (int j = 0; j < 4; j++) {
                gi[j]   = 1.0f / (1.0f + expf(-w_i[b0 + j]));
                const float gl = 1.0f / (1.0f + expf(-w_l[b0 + j]));
                c1[j]   = 1.0f - gl;
                glaw[j] = gl * (expf(w_o[b0 + j] - mx) / ssum);
            }
        }

        // h_start: fold over previous chunks' D (len-dependent decay)
        float hh[4] = {0, 0, 0, 0};
        {
            float c68[4], c72[4];
            #pragma unroll
            for (int j = 0; j < 4; j++) {
                const float x2  = c1[j] * c1[j];
                const float x4  = x2 * x2;
                const float x8  = x4 * x4;
                const float x16 = x8 * x8;
                const float x32 = x16 * x16;
                const float x64 = x32 * x32;
                c68[j] = x64 * x4;
                c72[j] = c68[j] * x4;
            }
            #pragma unroll 2
            for (int k = 0; k < chunk; k++) {
                const float4 D = ((const float4*)g_D)[k * L4 + lane4];
                const bool big = (k >= 14);
                hh[0] = (big ? c72[0] : c68[0]) * hh[0] + D.x;
                hh[1] = (big ? c72[1] : c68[1]) * hh[1] + D.y;
                hh[2] = (big ? c72[2] : c68[2]) * hh[2] + D.z;
                hh[3] = (big ? c72[3] : c68[3]) * hh[3] + D.w;
            }
        }

        const float4 s0v = ((const float4*)g_sstart)[chunk * L4 + lane4];
        float s[4] = {s0v.x, s0v.y, s0v.z, s0v.w};
        float4* H4 = (float4*)H + (size_t)t0 * L4 + lane4;

        #pragma unroll 2
        for (int t4 = 0; t4 < nG; t4++) {
            const float4 P4 = smP4[t4 * 32 + sl];
            const float4 T4 = smT4[t4 * 32 + sl];
            const float* Pv = &P4.x;
            const float* Tv = &T4.x;
            #pragma unroll
            for (int u = 0; u < 4; u++) {
                const int k = t4 * 4 + u;
                const float tpos = fmaxf(Tv[u], 0.0f);
                const float pneg = (Tv[u] < 0.0f) ? Pv[u] : 0.0f;
                const float ppos = (Tv[u] > 0.0f) ? Pv[u] : 0.0f;
                float hn[4];
                float qa = 0.0f;
                #pragma unroll
                for (int j = 0; j < 4; j++) {
                    const float sm  = tpos * melt[j];
                    const float m   = fminf(sm, s[j]);
                    s[j] = (s[j] - m) + pneg;
                    const float u2  = fmaf(ppos + m, gi[j], hh[j]);
                    hn[j] = c1[j] * u2;            // h - q + xin
                    hh[j] = hn[j];
                    qa = fmaf(u2, glaw[j], qa);    // q*a = u2*gl*a
                }
                __stcs(&H4[(size_t)k * L4], make_float4(hn[0], hn[1], hn[2], hn[3]));

                qa += __shfl_xor_sync(0xFFFFFFFFu, qa, 1);
                qa += __shfl_xor_sync(0xFFFFFFFFu, qa, 2);
                if (bg == 0) __stcs(&Q[(t0 + k) * NS + site], qa);
            }
        }
    }
}

extern "C" void kernel_launch(void* const* d_in, const int* in_sizes, int n_in,
                              void* d_out, int out_size)
{
    const float* P   = (const float*)d_in[0];
    const float* T   = (const float*)d_in[1];
    const float* w_i = (const float*)d_in[2];
    const float* w_o = (const float*)d_in[3];
    const float* w_l = (const float*)d_in[4];
    const float* w_s = (const float*)d_in[5];

    float* Q = (float*)d_out;
    float* H = Q + (size_t)NT * NS;
    float* S = H + (size_t)NT * NS * NH;

    waternet_fused<<<NBLOCKS, BLK>>>(P, T, w_i, w_o, w_l, w_s, Q, H, S);
}

// round 17
// speedup vs baseline: 1.0365x; 1.0365x over previous
#include <cuda_runtime.h>
#include <math.h>

// WaterNetModel: chunk-parallel scan, fused persistent kernel.
// Round 17: R15 structure (symmetric lockstep grid_syncs — asymmetric/async
// all lose) + R16's safe trims (E-rescale, chunk-15 A-skip) + load-batched
// prefix folds: s_start/h_start folds batch 4 iterations' L2 loads into regs
// before the dependent max-plus/affine updates (chain 30x250 -> ~8x250 cyc),
// shrinking the chunk-15 straggler that defines the critical path.
// Snow: s' = max(s + a, b) (max-plus); A = Psum - melt*Tsum.
// Bucket: h' = c1*(h + xin), constant c1 (affine).
// Outputs: Q [NT,NS] | H [NT,NS,NH] | S [NT,NS,NH].

#define NT 1096
#define NS 2048
#define NH 16
#define C16 16
#define CA 32
#define LANES (NS * NH)        // 32768
#define L4    (LANES / 4)      // 8192
#define NTHREADS (C16 * L4)    // 131072
#define BLK 128
#define NBLOCKS (NTHREADS / BLK)  // 1024 (<= 8*148 = 1184 resident slots)

// scratch
__device__ float g_Ps[CA * NS];          // per-A-chunk sum of pneg
__device__ float g_Ts[CA * NS];          // per-A-chunk sum of tpos
__device__ float g_B[CA * LANES];        // snow compose floor
__device__ float g_sstart[C16 * LANES];  // C-chunk start snow state (self-RW)
__device__ float g_D[C16 * LANES];       // bucket chunk offsets

__device__ unsigned g_bar = 0;
__device__ unsigned g_gen = 0;

__device__ __forceinline__ void grid_sync()
{
    __syncthreads();
    if (threadIdx.x == 0) {
        __threadfence();
        unsigned gen = *(volatile unsigned*)&g_gen;
        unsigned arr = atomicAdd(&g_bar, 1u);
        if (arr == (unsigned)gridDim.x - 1u) {
            g_bar = 0;
            __threadfence();
            *(volatile unsigned*)&g_gen = gen + 1u;
        } else {
            while (*(volatile unsigned*)&g_gen == gen) { __nanosleep(32); }
        }
        __threadfence();
    }
    __syncthreads();
}

// C-chunk geometry: chunks 0..13 len 68, chunks 14..15 len 72
__device__ __forceinline__ int c_t0(int c)  { return (c < 14) ? 68 * c : 952 + 72 * (c - 14); }
__device__ __forceinline__ int c_len(int c) { return (c < 14) ? 68 : 72; }

__global__ __launch_bounds__(BLK, 8)
void waternet_fused(const float* __restrict__ P, const float* __restrict__ T,
                    const float* __restrict__ w_i, const float* __restrict__ w_o,
                    const float* __restrict__ w_l, const float* __restrict__ w_s,
                    float* __restrict__ Q, float* __restrict__ H,
                    float* __restrict__ S)
{
    // time-packed slab: sm[t4][site] = float4 of 4 consecutive timesteps
    __shared__ float4 smP4[18 * 32];   // 9 KB
    __shared__ float4 smT4[18 * 32];   // 9 KB

    const int tid = threadIdx.x;
    const int g   = blockIdx.x * BLK + tid;   // [0, NTHREADS)

    const int lane4 = g & (L4 - 1);
    const int chunk = g >> 13;
    const int site  = lane4 >> 2;
    const int bg    = tid & 3;
    const int b0    = bg * 4;
    const int sl    = tid >> 2;                // local site [0,32)

    const int t0  = c_t0(chunk);
    const int len = c_len(chunk);
    const int nG  = len >> 2;                  // 17 or 18 groups of 4

    // =============== Stage slab (once; reused by A, C, E) ================
    {
        const int s0 = ((blockIdx.x * BLK) & (L4 - 1)) >> 2;
        const int nE = nG * 32;
        for (int e = tid; e < nE; e += BLK) {
            const int t4 = e >> 5, j = e & 31;
            const float* Pg = P + (t0 + 4 * t4) * NS + s0 + j;
            const float* Tg = T + (t0 + 4 * t4) * NS + s0 + j;
            float4 p, t;
            p.x = __ldg(Pg);          t.x = __ldg(Tg);
            p.y = __ldg(Pg + NS);     t.y = __ldg(Tg + NS);
            p.z = __ldg(Pg + 2 * NS); t.z = __ldg(Tg + 2 * NS);
            p.w = __ldg(Pg + 3 * NS); t.w = __ldg(Tg + 3 * NS);
            smP4[t4 * 32 + j] = p;
            smT4[t4 * 32 + j] = t;
        }
    }

    float melt[4];
    #pragma unroll
    for (int j = 0; j < 4; j++) melt[j] = expf(w_s[b0 + j]) + 1.0f;

    __syncthreads();

    // =============== Phase A: own chunk's two half-summaries =============
    // chunk 15's summaries are never folded -> skip
    if (chunk != C16 - 1) {
        #pragma unroll
        for (int hlf = 0; hlf < 2; hlf++) {
            const int t40 = hlf ? 9 : 0;       // halves [0,36) and [36,len)
            const int t41 = hlf ? nG : 9;
            float B[4] = {-INFINITY, -INFINITY, -INFINITY, -INFINITY};
            float Ps = 0.0f, Ts = 0.0f;
            for (int t4 = t40; t4 < t41; t4++) {
                const float4 P4 = smP4[t4 * 32 + sl];
                const float4 T4 = smT4[t4 * 32 + sl];
                const float* Pv = &P4.x;
                const float* Tv = &T4.x;
                #pragma unroll
                for (int u = 0; u < 4; u++) {
                    const float tpos = fmaxf(Tv[u], 0.0f);
                    const float pneg = (Tv[u] < 0.0f) ? Pv[u] : 0.0f;
                    Ps += pneg;
                    Ts += tpos;
                    #pragma unroll
                    for (int j = 0; j < 4; j++) {
                        const float a = fmaf(tpos, -melt[j], pneg);
                        B[j] = fmaxf(B[j] + a, pneg);
                    }
                }
            }
            const int ca = 2 * chunk + hlf;
            ((float4*)g_B)[ca * L4 + lane4] = make_float4(B[0], B[1], B[2], B[3]);
            if (bg == 0) {
                g_Ps[ca * NS + site] = Ps;
                g_Ts[ca * NS + site] = Ts;
            }
        }
    }
    grid_sync();

    // =============== Phase C: fold s_start, replay snow, write S =========
    {
        float c1[4], cg[4];
        #pragma unroll
        for (int j = 0; j < 4; j++) {
            const float gi = 1.0f / (1.0f + expf(-w_i[b0 + j]));
            c1[j] = 1.0f - 1.0f / (1.0f + expf(-w_l[b0 + j]));
            cg[j] = c1[j] * gi;
        }

        // load-batched s_start fold (batch 4; nca even so remainder is 0 or 2)
        float s[4] = {0, 0, 0, 0};
        {
            const int nca = chunk * 2;
            int ca = 0;
            for (; ca + 4 <= nca; ca += 4) {
                float4 Bv[4];
                float Psv[4], Tsv[4];
                #pragma unroll
                for (int q = 0; q < 4; q++) {
                    Psv[q] = g_Ps[(ca + q) * NS + site];
                    Tsv[q] = g_Ts[(ca + q) * NS + site];
                    Bv[q]  = ((const float4*)g_B)[(ca + q) * L4 + lane4];
                }
                #pragma unroll
                for (int q = 0; q < 4; q++) {
                    s[0] = fmaxf(s[0] + fmaf(-melt[0], Tsv[q], Psv[q]), Bv[q].x);
                    s[1] = fmaxf(s[1] + fmaf(-melt[1], Tsv[q], Psv[q]), Bv[q].y);
                    s[2] = fmaxf(s[2] + fmaf(-melt[2], Tsv[q], Psv[q]), Bv[q].z);
                    s[3] = fmaxf(s[3] + fmaf(-melt[3], Tsv[q], Psv[q]), Bv[q].w);
                }
            }
            for (; ca < nca; ca++) {
                const float Ps = g_Ps[ca * NS + site];
                const float Ts = g_Ts[ca * NS + site];
                const float4 B = ((const float4*)g_B)[ca * L4 + lane4];
                s[0] = fmaxf(s[0] + fmaf(-melt[0], Ts, Ps), B.x);
                s[1] = fmaxf(s[1] + fmaf(-melt[1], Ts, Ps), B.y);
                s[2] = fmaxf(s[2] + fmaf(-melt[2], Ts, Ps), B.z);
                s[3] = fmaxf(s[3] + fmaf(-melt[3], Ts, Ps), B.w);
            }
        }
        ((float4*)g_sstart)[chunk * L4 + lane4] = make_float4(s[0], s[1], s[2], s[3]);

        // rescaled bucket accumulator: E' = fma(c1, E, t1); D = cg*E at end
        float E[4] = {0, 0, 0, 0};
        float4* S4 = (float4*)S + (size_t)t0 * L4 + lane4;

        #pragma unroll 2
        for (int t4 = 0; t4 < nG; t4++) {
            const float4 P4 = smP4[t4 * 32 + sl];
            const float4 T4 = smT4[t4 * 32 + sl];
            const float* Pv = &P4.x;
            const float* Tv = &T4.x;
            #pragma unroll
            for (int u = 0; u < 4; u++) {
                const int k = t4 * 4 + u;
                const float tpos = fmaxf(Tv[u], 0.0f);
                const float pneg = (Tv[u] < 0.0f) ? Pv[u] : 0.0f;
                const float ppos = (Tv[u] > 0.0f) ? Pv[u] : 0.0f;
                float sn[4];
                #pragma unroll
                for (int j = 0; j < 4; j++) {
                    const float sm = tpos * melt[j];
                    const float m  = fminf(sm, s[j]);
                    sn[j] = (s[j] - m) + pneg;
                    E[j] = fmaf(c1[j], E[j], ppos + m);
                    s[j] = sn[j];
                }
                __stcs(&S4[(size_t)k * L4], make_float4(sn[0], sn[1], sn[2], sn[3]));
            }
        }
        ((float4*)g_D)[chunk * L4 + lane4] =
            make_float4(cg[0] * E[0], cg[1] * E[1], cg[2] * E[2], cg[3] * E[3]);
    }
    grid_sync();

    // =============== Phase E: h_start fold, replay, write H and Q ========
    {
        float gi[4], c1[4], glaw[4];
        {
            float mx = w_o[0];
            #pragma unroll
            for (int j = 1; j < NH; j++) mx = fmaxf(mx, w_o[j]);
            float ssum = 0.0f;
            #pragma unroll
            for (int j = 0; j < NH; j++) ssum += expf(w_o[j] - mx);
            #pragma unroll
            for (int j = 0; j < 4; j++) {
                gi[j]   = 1.0f / (1.0f + expf(-w_i[b0 + j]));
                const float gl = 1.0f / (1.0f + expf(-w_l[b0 + j]));
                c1[j]   = 1.0f - gl;
                glaw[j] = gl * (expf(w_o[b0 + j] - mx) / ssum);
            }
        }

        // load-batched h_start fold (batch 4 + remainder)
        float hh[4] = {0, 0, 0, 0};
        {
            float c68[4], c72[4];
            #pragma unroll
            for (int j = 0; j < 4; j++) {
                const float x2  = c1[j] * c1[j];
                const float x4  = x2 * x2;
                const float x8  = x4 * x4;
                const float x16 = x8 * x8;
                const float x32 = x16 * x16;
                const float x64 = x32 * x32;
                c68[j] = x64 * x4;
                c72[j] = c68[j] * x4;
            }
            int k = 0;
            for (; k + 4 <= chunk; k += 4) {
                float4 Dv[4];
                #pragma unroll
                for (int q = 0; q < 4; q++)
                    Dv[q] = ((const float4*)g_D)[(k + q) * L4 + lane4];
                #pragma unroll
                for (int q = 0; q < 4; q++) {
                    const bool big = (k + q >= 14);
                    hh[0] = (big ? c72[0] : c68[0]) * hh[0] + Dv[q].x;
                    hh[1] = (big ? c72[1] : c68[1]) * hh[1] + Dv[q].y;
                    hh[2] = (big ? c72[2] : c68[2]) * hh[2] + Dv[q].z;
                    hh[3] = (big ? c72[3] : c68[3]) * hh[3] + Dv[q].w;
                }
            }
            for (; k < chunk; k++) {
                const float4 D = ((const float4*)g_D)[k * L4 + lane4];
                const bool big = (k >= 14);
                hh[0] = (big ? c72[0] : c68[0]) * hh[0] + D.x;
                hh[1] = (big ? c72[1] : c68[1]) * hh[1] + D.y;
                hh[2] = (big ? c72[2] : c68[2]) * hh[2] + D.z;
                hh[3] = (big ? c72[3] : c68[3]) * hh[3] + D.w;
            }
        }

        const float4 s0v = ((const float4*)g_sstart)[chunk * L4 + lane4];
        float s[4] = {s0v.x, s0v.y, s0v.z, s0v.w};
        float4* H4 = (float4*)H + (size_t)t0 * L4 + lane4;

        #pragma unroll 2
        for (int t4 = 0; t4 < nG; t4++) {
            const float4 P4 = smP4[t4 * 32 + sl];
            const float4 T4 = smT4[t4 * 32 + sl];
            const float* Pv = &P4.x;
            const float* Tv = &T4.x;
            #pragma unroll
            for (int u = 0; u < 4; u++) {
                const int k = t4 * 4 + u;
                const float tpos = fmaxf(Tv[u], 0.0f);
                const float pneg = (Tv[u] < 0.0f) ? Pv[u] : 0.0f;
                const float ppos = (Tv[u] > 0.0f) ? Pv[u] : 0.0f;
                float hn[4];
                float qa = 0.0f;
                #pragma unroll
                for (int j = 0; j < 4; j++) {
                    const float sm  = tpos * melt[j];
                    const float m   = fminf(sm, s[j]);
                    s[j] = (s[j] - m) + pneg;
                    const float u2  = fmaf(ppos + m, gi[j], hh[j]);
                    hn[j] = c1[j] * u2;            // h - q + xin
                    hh[j] = hn[j];
                    qa = fmaf(u2, glaw[j], qa);    // q*a = u2*gl*a
                }
                __stcs(&H4[(size_t)k * L4], make_float4(hn[0], hn[1], hn[2], hn[3]));

                qa += __shfl_xor_sync(0xFFFFFFFFu, qa, 1);
                qa += __shfl_xor_sync(0xFFFFFFFFu, qa, 2);
                if (bg == 0) __stcs(&Q[(t0 + k) * NS + site], qa);
            }
        }
    }
}

extern "C" void kernel_launch(void* const* d_in, const int* in_sizes, int n_in,
                              void* d_out, int out_size)
{
    const float* P   = (const float*)d_in[0];
    const float* T   = (const float*)d_in[1];
    const float* w_i = (const float*)d_in[2];
    const float* w_o = (const float*)d_in[3];
    const float* w_l = (const float*)d_in[4];
    const float* w_s = (const float*)d_in[5];

    float* Q = (float*)d_out;
    float* H = Q + (size_t)NT * NS;
    float* S = H + (size_t)NT * NS * NH;

    waternet_fused<<<NBLOCKS, BLK>>>(P, T, w_i, w_o, w_l, w_s, Q, H, S);
}